// round 14
// baseline (speedup 1.0000x reference)
#include <cuda_runtime.h>
#include <cuda_bf16.h>
#include <math.h>

#define NN 50000
#define HH 128
#define NPAD 50048            // 391*128, padded rows (zero-init)
#define TN 16                 // nodes per tile (16*8 = 128 rows)
#define NTILES (NN/TN)        // 3125

// ---------------- scratch (__device__ globals; zero-initialized) ----------------
__device__ float g_T[2*128*128];              // Q0 = vf@Wd | Q1 = vf@Wa
__device__ float g_G[384*384];                // [Q0@U0 ; Q1@U1 ; Wiou]
__device__ float g_qv[128];                   // Qf @ Vf
__device__ float g_px[NN];                    // x . qv  (per node)
__device__ __nv_bfloat16 g_Zh[(size_t)NPAD*384];  // Z hi (bf16 split)
__device__ __nv_bfloat16 g_Zl[(size_t)NPAD*384];  // Z lo
__device__ float g_IOU[(size_t)NPAD*384];
__device__ float g_cred[(size_t)NN*128];

// ================= helpers =================
__device__ __forceinline__ unsigned smem_u32(const void* p) {
    unsigned a;
    asm("{ .reg .u64 t; cvta.to.shared.u64 t, %1; cvt.u32.u64 %0, t; }" : "=r"(a) : "l"(p));
    return a;
}

__device__ __forceinline__ void ldsm4(unsigned r[4], unsigned addr) {
    asm volatile("ldmatrix.sync.aligned.m8n8.x4.shared.b16 {%0,%1,%2,%3}, [%4];"
                 : "=r"(r[0]), "=r"(r[1]), "=r"(r[2]), "=r"(r[3]) : "r"(addr));
}

__device__ __forceinline__ void mma16816(float c[4], const unsigned a[4],
                                         unsigned b0, unsigned b1) {
    asm volatile("mma.sync.aligned.m16n8k16.row.col.f32.bf16.bf16.f32 "
                 "{%0,%1,%2,%3}, {%4,%5,%6,%7}, {%8,%9}, {%0,%1,%2,%3};"
                 : "+f"(c[0]), "+f"(c[1]), "+f"(c[2]), "+f"(c[3])
                 : "r"(a[0]), "r"(a[1]), "r"(a[2]), "r"(a[3]), "r"(b0), "r"(b1));
}

#define CP_ASYNC16(dst, src) \
    asm volatile("cp.async.cg.shared.global [%0], [%1], 16;" :: "r"(dst), "l"(src) : "memory")
#define CP_COMMIT()  asm volatile("cp.async.commit_group;" ::: "memory")
#define CP_WAIT1()   asm volatile("cp.async.wait_group 1;" ::: "memory")
#define CP_WAIT0()   asm volatile("cp.async.wait_group 0;" ::: "memory")

// fp32 -> bf16 hi/lo split, 2 elements packed per word
__device__ __forceinline__ void split2(float a, float b, unsigned& hi, unsigned& lo) {
    __nv_bfloat16 ha = __float2bfloat16_rn(a);
    __nv_bfloat16 hb = __float2bfloat16_rn(b);
    __nv_bfloat16 la = __float2bfloat16_rn(a - __bfloat162float(ha));
    __nv_bfloat16 lb = __float2bfloat16_rn(b - __bfloat162float(hb));
    hi = ((unsigned)__bfloat16_as_ushort(hb) << 16) | (unsigned)__bfloat16_as_ushort(ha);
    lo = ((unsigned)__bfloat16_as_ushort(lb) << 16) | (unsigned)__bfloat16_as_ushort(la);
}

__device__ __forceinline__ float shflr(float v, int m) {
    return __shfl_xor_sync(0xffffffffu, v, m);
}

// ---------------- K1a: Q0 = vf@Wd, Q1 = vf@Wa (128x128 each) ----------------
__global__ void k1a(const float* __restrict__ Wa, const float* __restrict__ Wd,
                    const float* __restrict__ vf) {
    int idx = blockIdx.x * blockDim.x + threadIdx.x;
    if (idx >= 2*128*128) return;
    int which = idx >> 14;
    int rem   = idx & 16383;
    int m = rem >> 7, j = rem & 127;
    const float* W = which ? Wa : Wd;
    float s = 0.f;
#pragma unroll 8
    for (int z = 0; z < 128; z++) s += vf[m*128+z] * W[z*128+j];
    g_T[idx] = s;
}

// ---------------- K1b: G = [Q0@U0 ; Q1@U1 ; Wiou]; qv = Qf@Vf ----------------
__global__ void k1b(const float* __restrict__ Uiou, const float* __restrict__ Wiou,
                    const float* __restrict__ Qf, const float* __restrict__ Vf) {
    int idx = blockIdx.x * blockDim.x + threadIdx.x;
    if (idx < 2*128*384) {
        int which = idx / (128*384);
        int rem   = idx - which*(128*384);
        int m = rem / 384, j = rem - m*384;
        const float* Q = g_T + which*(128*128);
        const float* U = Uiou + which*(128*384);
        float s = 0.f;
#pragma unroll 8
        for (int z = 0; z < 128; z++) s += Q[m*128+z] * U[z*384+j];
        g_G[idx] = s;
    } else if (idx < 3*128*384) {
        int rem = idx - 2*128*384;
        g_G[idx] = Wiou[rem];
    } else if (idx < 3*128*384 + 128) {
        int m = idx - 3*128*384;
        float s = 0.f;
#pragma unroll 8
        for (int j = 0; j < 128; j++) s += Qf[m*128+j] * Vf[j];
        g_qv[m] = s;
    }
}

// ---------------- K1c: px = x . qv ; x -> Zh/Zl cols [256,384) ----------------
__global__ void k1c(const float* __restrict__ x) {
    int idx = blockIdx.x * blockDim.x + threadIdx.x;   // NN*32
    if (idx >= NN*32) return;
    int n = idx >> 5;
    int j = (idx & 31) * 4;
    float4 v = *(const float4*)(x + (size_t)n*128 + j);
    unsigned h0, l0, h1, l1;
    split2(v.x, v.y, h0, l0);
    split2(v.z, v.w, h1, l1);
    size_t o = (size_t)n*384 + 256 + j;
    *(unsigned*)(g_Zh + o)     = h0;
    *(unsigned*)(g_Zh + o + 2) = h1;
    *(unsigned*)(g_Zl + o)     = l0;
    *(unsigned*)(g_Zl + o + 2) = l1;
    float p = v.x*g_qv[j] + v.y*g_qv[j+1] + v.z*g_qv[j+2] + v.w*g_qv[j+3];
#pragma unroll
    for (int m = 1; m < 32; m <<= 1) p += shflr(p, m);
    if ((idx & 31) == 0) g_px[n] = p;
}

// ---------------- K2 (fused, 4x4 warp remap: 32 rows x 32 cols per warp) ----------------
// Weights resident: Kh Kl Zh Zl Dh Dl (6 x 32KB). A: Ah 16K + Al 16K (single buffer).
// pb (4 col-group partial dots, 2KB) aliases A (post-MMA use only).
#define K2_AB   196608
#define K2_SMEM 229376
__global__ void __launch_bounds__(512, 1)
k2(const float* __restrict__ hmail, const float* __restrict__ cmail,
   const float* __restrict__ Kf, const float* __restrict__ Vf,
   const float* __restrict__ Of, const float* __restrict__ Zf,
   const int* __restrict__ etype) {
    extern __shared__ char smc[];
    const unsigned smb = smem_u32(smc);
    const int tid = threadIdx.x, wid = tid >> 5, lane = tid & 31;
    const int wr = wid & 3, wc = wid >> 2;          // 4 row groups x 4 col groups
    const unsigned AB = smb + K2_AB;
    float* pb = (float*)(smc + K2_AB);              // alias (post-MMA use only)

    // weight prep: B[n][k] = W[k][n]; bf16 hi/lo; row stride 256B, XOR swizzle
    for (int idx = tid; idx < 128*128; idx += 512) {
        int n = idx & 127, k = idx >> 7;
        unsigned off = (unsigned)(n*256 + ((2*k) ^ ((n & 7) << 4)));
        float kf = Kf[k*128 + n];
        __nv_bfloat16 kh = __float2bfloat16_rn(kf);
        __nv_bfloat16 kl = __float2bfloat16_rn(kf - __bfloat162float(kh));
        *(__nv_bfloat16*)(smc + 0*32768 + off) = kh;
        *(__nv_bfloat16*)(smc + 1*32768 + off) = kl;
        float zf = Zf[k*128 + n];
        float d  = Of[k*128 + n] - zf;
        __nv_bfloat16 zh = __float2bfloat16_rn(zf);
        __nv_bfloat16 zl = __float2bfloat16_rn(zf - __bfloat162float(zh));
        __nv_bfloat16 dh = __float2bfloat16_rn(d);
        __nv_bfloat16 dl = __float2bfloat16_rn(d - __bfloat162float(dh));
        *(__nv_bfloat16*)(smc + 2*32768 + off) = zh;
        *(__nv_bfloat16*)(smc + 3*32768 + off) = zl;
        *(__nv_bfloat16*)(smc + 4*32768 + off) = dh;
        *(__nv_bfloat16*)(smc + 5*32768 + off) = dl;
    }
    __syncthreads();

    for (int tile = blockIdx.x; tile < NTILES; tile += gridDim.x) {
        const size_t rbase = (size_t)tile * 128;

        unsigned mlo[2], mhi[2];
#pragma unroll
        for (int t = 0; t < 2; t++) {
            mlo[t] = (etype[rbase + wr*32 + t*16 + (lane >> 2)]     != 0) ? 0xffffffffu : 0u;
            mhi[t] = (etype[rbase + wr*32 + t*16 + 8 + (lane >> 2)] != 0) ? 0xffffffffu : 0u;
        }

        float acck[2][2][2][4], accf[2][2][2][4];   // [t][g][s][4]
#pragma unroll
        for (int t = 0; t < 2; t++)
#pragma unroll
            for (int g = 0; g < 2; g++)
#pragma unroll
                for (int s = 0; s < 2; s++)
#pragma unroll
                    for (int q = 0; q < 4; q++) { acck[t][g][s][q] = 0.f; accf[t][g][s][q] = 0.f; }

        for (int chunk = 0; chunk < 2; chunk++) {
            // convert A chunk [128 rows x 64 k] -> Ah/Al
            {
                const int row = tid >> 2, seg = tid & 3;
                const float* src = hmail + (rbase + row)*128 + chunk*64 + seg*16;
                const unsigned rsw = (unsigned)((row & 7) << 4);
#pragma unroll
                for (int i = 0; i < 4; i++) {
                    float4 v = ((const float4*)src)[i];
                    unsigned h0, l0, h1, l1;
                    split2(v.x, v.y, h0, l0);
                    split2(v.z, v.w, h1, l1);
                    int j = seg*16 + i*4;
                    unsigned bo = (unsigned)(row*128 + ((2*j) ^ rsw));
                    *(unsigned*)(smc + K2_AB + bo)             = h0;
                    *(unsigned*)(smc + K2_AB + bo + 4)         = h1;
                    *(unsigned*)(smc + K2_AB + 16384 + bo)     = l0;
                    *(unsigned*)(smc + K2_AB + 16384 + bo + 4) = l1;
                }
            }
            __syncthreads();
            // MMA: warp = rows wr*32..+31, cols wc*32..+31
            {
                const int bn_l = (lane & 7) + (lane >> 4) * 8;
                const int bkb_l = ((lane >> 3) & 1) * 16;
                const int ar_l = (lane & 7) + ((lane >> 3) & 1) * 8;
#pragma unroll
                for (int kk = 0; kk < 4; kk++) {
                    const unsigned akb = (unsigned)(kk*32 + (lane >> 4) * 16);
                    const int bkb = chunk*128 + kk*32 + bkb_l;
#pragma unroll
                    for (int g = 0; g < 2; g++) {
                        int bn = wc*32 + g*16 + bn_l;
                        unsigned boff = (unsigned)(bn*256) +
                                        ((unsigned)bkb ^ ((unsigned)(bn & 7) << 4));
                        unsigned kh[4], kl[4], zh[4], zl[4], dh[4], dl[4];
                        ldsm4(kh, smb + 0*32768 + boff);
                        ldsm4(kl, smb + 1*32768 + boff);
                        ldsm4(zh, smb + 2*32768 + boff);
                        ldsm4(zl, smb + 3*32768 + boff);
                        ldsm4(dh, smb + 4*32768 + boff);
                        ldsm4(dl, smb + 5*32768 + boff);
#pragma unroll
                        for (int t = 0; t < 2; t++) {
                            int arow = wr*32 + t*16 + ar_l;
                            unsigned aoff = (unsigned)(arow*128) +
                                            (akb ^ ((unsigned)(arow & 7) << 4));
                            unsigned ah[4], al[4], aeh[4], ael[4];
                            ldsm4(ah, AB + aoff);
                            ldsm4(al, AB + 16384 + aoff);
                            aeh[0] = ah[0] & mlo[t]; aeh[1] = ah[1] & mhi[t];
                            aeh[2] = ah[2] & mlo[t]; aeh[3] = ah[3] & mhi[t];
                            ael[0] = al[0] & mlo[t]; ael[1] = al[1] & mhi[t];
                            ael[2] = al[2] & mlo[t]; ael[3] = al[3] & mhi[t];
#pragma unroll
                            for (int s = 0; s < 2; s++) {
                                mma16816(acck[t][g][s], ah,  kh[s*2], kh[s*2+1]);
                                mma16816(acck[t][g][s], ah,  kl[s*2], kl[s*2+1]);
                                mma16816(acck[t][g][s], al,  kh[s*2], kh[s*2+1]);
                                mma16816(accf[t][g][s], ah,  zh[s*2], zh[s*2+1]);
                                mma16816(accf[t][g][s], ah,  zl[s*2], zl[s*2+1]);
                                mma16816(accf[t][g][s], al,  zh[s*2], zh[s*2+1]);
                                mma16816(accf[t][g][s], aeh, dh[s*2], dh[s*2+1]);
                                mma16816(accf[t][g][s], aeh, dl[s*2], dl[s*2+1]);
                                mma16816(accf[t][g][s], ael, dh[s*2], dh[s*2+1]);
                            }
                        }
                    }
                }
            }
            __syncthreads();
        }

        // ---- f epilogue: f = sigmoid(accf); c_red = sum over 8 mail rows ----
#pragma unroll
        for (int t = 0; t < 2; t++) {
            const int rlo = wr*32 + t*16 + (lane >> 2);
            const int rhi = rlo + 8;
            const int node0 = tile*TN + wr*4 + t*2, node1 = node0 + 1;
#pragma unroll
            for (int g = 0; g < 2; g++)
#pragma unroll
                for (int s = 0; s < 2; s++) {
                    int col = wc*32 + g*16 + s*8 + (lane & 3)*2;
                    float2 c0 = *(const float2*)(cmail + (rbase + rlo)*128 + col);
                    float2 c1 = *(const float2*)(cmail + (rbase + rhi)*128 + col);
                    float v0 = c0.x / (1.f + expf(-accf[t][g][s][0]));
                    float v1 = c0.y / (1.f + expf(-accf[t][g][s][1]));
                    float v2 = c1.x / (1.f + expf(-accf[t][g][s][2]));
                    float v3 = c1.y / (1.f + expf(-accf[t][g][s][3]));
#pragma unroll
                    for (int m = 4; m < 32; m <<= 1) {
                        v0 += shflr(v0, m); v1 += shflr(v1, m);
                        v2 += shflr(v2, m); v3 += shflr(v3, m);
                    }
                    if (lane < 4) {
                        int c = wc*32 + g*16 + s*8 + lane*2;
                        *(float2*)(g_cred + (size_t)node0*128 + c) = make_float2(v0, v1);
                    } else if (lane < 8) {
                        int c = wc*32 + g*16 + s*8 + (lane - 4)*2;
                        *(float2*)(g_cred + (size_t)node1*128 + c) = make_float2(v2, v3);
                    }
                }
        }

        // ---- k epilogue: partial dots with Vf -> pb (4 col-group slices) ----
#pragma unroll
        for (int t = 0; t < 2; t++) {
            const int rlo = wr*32 + t*16 + (lane >> 2);
            const int rhi = rlo + 8;
            float plo = 0.f, phi = 0.f;
#pragma unroll
            for (int g = 0; g < 2; g++)
#pragma unroll
                for (int s = 0; s < 2; s++) {
                    int c = wc*32 + g*16 + s*8 + (lane & 3)*2;
                    float vf0 = __ldg(Vf + c), vf1 = __ldg(Vf + c + 1);
                    plo += acck[t][g][s][0]*vf0 + acck[t][g][s][1]*vf1;
                    phi += acck[t][g][s][2]*vf0 + acck[t][g][s][3]*vf1;
                }
            plo += shflr(plo, 1); plo += shflr(plo, 2);
            phi += shflr(phi, 1); phi += shflr(phi, 2);
            if ((lane & 3) == 0) {
                pb[wc*128 + rlo] = plo;
                pb[wc*128 + rhi] = phi;
            }
        }
        __syncthreads();

#pragma unroll
        for (int t = 0; t < 2; t++) {
            const int rlo = wr*32 + t*16 + (lane >> 2);
            const int rhi = rlo + 8;
            const int node0 = tile*TN + wr*4 + t*2, node1 = node0 + 1;

            float p_lo = pb[rlo] + pb[128 + rlo] + pb[256 + rlo] + pb[384 + rlo];
            float p_hi = pb[rhi] + pb[128 + rhi] + pb[256 + rhi] + pb[384 + rhi];

            float e_lo = (float)etype[rbase + rlo];
            float e_hi = (float)etype[rbase + rhi];
            float sc_lo = tanhf(g_px[node0] + p_lo);
            float sc_hi = tanhf(g_px[node1] + p_hi);

            float mx0 = sc_lo, mx1 = sc_hi, sm0 = e_lo, sm1 = e_hi;
#pragma unroll
            for (int m = 4; m < 32; m <<= 1) {
                mx0 = fmaxf(mx0, shflr(mx0, m));
                mx1 = fmaxf(mx1, shflr(mx1, m));
                sm0 += shflr(sm0, m);
                sm1 += shflr(sm1, m);
            }
            float ex0 = expf(sc_lo - mx0), ex1 = expf(sc_hi - mx1);
            float se0 = ex0, se1 = ex1;
#pragma unroll
            for (int m = 4; m < 32; m <<= 1) { se0 += shflr(se0, m); se1 += shflr(se1, m); }
            float w0 = ex0 / se0, w1 = ex1 / se1;
            float mod0 = sm0 * 0.125f, mod1 = sm1 * 0.125f;
            float c1_lo = w0 * (1.f - mod0) * e_lo;
            float c0_lo = w0 * mod0 * (1.f - e_lo);
            float c1_hi = w1 * (1.f - mod1) * e_hi;
            float c0_hi = w1 * mod1 * (1.f - e_hi);

#pragma unroll
            for (int g = 0; g < 2; g++)
#pragma unroll
                for (int s = 0; s < 2; s++) {
                    float b00 = c0_lo*acck[t][g][s][0], b01 = c0_lo*acck[t][g][s][1];
                    float a00 = c1_lo*acck[t][g][s][0], a01 = c1_lo*acck[t][g][s][1];
                    float b10 = c0_hi*acck[t][g][s][2], b11 = c0_hi*acck[t][g][s][3];
                    float a10 = c1_hi*acck[t][g][s][2], a11 = c1_hi*acck[t][g][s][3];
#pragma unroll
                    for (int m = 4; m < 32; m <<= 1) {
                        b00 += shflr(b00, m); b01 += shflr(b01, m);
                        a00 += shflr(a00, m); a01 += shflr(a01, m);
                        b10 += shflr(b10, m); b11 += shflr(b11, m);
                        a10 += shflr(a10, m); a11 += shflr(a11, m);
                    }
                    if (lane < 4) {
                        int c = wc*32 + g*16 + s*8 + lane*2;
                        size_t ro = (size_t)node0 * 384;
                        unsigned hi, lo;
                        split2(b00, b01, hi, lo);
                        *(unsigned*)(g_Zh + ro + c) = hi;
                        *(unsigned*)(g_Zl + ro + c) = lo;
                        split2(a00, a01, hi, lo);
                        *(unsigned*)(g_Zh + ro + 128 + c) = hi;
                        *(unsigned*)(g_Zl + ro + 128 + c) = lo;
                    } else if (lane < 8) {
                        int c = wc*32 + g*16 + s*8 + (lane - 4)*2;
                        size_t ro = (size_t)node1 * 384;
                        unsigned hi, lo;
                        split2(b10, b11, hi, lo);
                        *(unsigned*)(g_Zh + ro + c) = hi;
                        *(unsigned*)(g_Zl + ro + c) = lo;
                        split2(a10, a11, hi, lo);
                        *(unsigned*)(g_Zh + ro + 128 + c) = hi;
                        *(unsigned*)(g_Zl + ro + 128 + c) = lo;
                    }
                }
        }
        __syncthreads();   // pb (aliases A) must be fully read before next convert
    }
}

// ---------------- K3a (mma.sync bf16, 3-term, cp.async double-buffered A) ----------------
// SMEM: Bh 96K | Bl 96K | A bufs 2 x (Ah 8K + Al 8K) = 229376 B
#define K3_BL   98304
#define K3_AB   196608
#define K3_SMEM 229376
__global__ void __launch_bounds__(512, 1)
k3a(const float* __restrict__ biou) {
    extern __shared__ char smc[];
    const unsigned smb = smem_u32(smc);
    const int tid = threadIdx.x, wid = tid >> 5, lane = tid & 31;
    const int wrow = wid & 7, ch = wid >> 3;
    const int jb = blockIdx.x * 128;           // output col block
    const unsigned AB = smb + K3_AB;

    // B fill: B[n][k] = G[k][jb+n], bf16 hi/lo, row stride 768B, XOR swizzle
    for (int idx = tid; idx < 128*384; idx += 512) {
        int k = idx % 384, n = idx / 384;
        float v = g_G[k*384 + jb + n];
        __nv_bfloat16 bh = __float2bfloat16_rn(v);
        __nv_bfloat16 bl = __float2bfloat16_rn(v - __bfloat162float(bh));
        unsigned off = (unsigned)(n*768 + ((2*k) ^ ((n & 7) << 4)));
        *(__nv_bfloat16*)(smc + off)          = bh;
        *(__nv_bfloat16*)(smc + K3_BL + off)  = bl;
    }
    __syncthreads();

    const int crow = tid >> 2, cseg = tid & 3;
    const unsigned csw = ((unsigned)((crow >> 1) & 3)) << 4;
    const unsigned cdo = (unsigned)(crow*64) + (((unsigned)cseg*16) ^ csw);

    for (int rt = blockIdx.y; rt < 391; rt += gridDim.y) {
        const size_t rbase = (size_t)rt * 128;

        {
            const size_t go = (rbase + crow)*384 + cseg*8;
            CP_ASYNC16(AB + cdo,        (const void*)(g_Zh + go));
            CP_ASYNC16(AB + 8192 + cdo, (const void*)(g_Zl + go));
            CP_COMMIT();
        }

        float acc[4][2][4];
#pragma unroll
        for (int g = 0; g < 4; g++)
#pragma unroll
            for (int s = 0; s < 2; s++)
#pragma unroll
                for (int q = 0; q < 4; q++) acc[g][s][q] = 0.f;

        for (int c = 0; c < 12; c++) {
            if (c < 11) {
                const size_t go = (rbase + crow)*384 + (c+1)*32 + cseg*8;
                unsigned dst = AB + (unsigned)(((c+1) & 1)*16384) + cdo;
                CP_ASYNC16(dst,        (const void*)(g_Zh + go));
                CP_ASYNC16(dst + 8192, (const void*)(g_Zl + go));
                CP_COMMIT();
                CP_WAIT1();
            } else {
                CP_WAIT0();
            }
            __syncthreads();
            {
                const int arow = wrow*16 + (lane & 7) + ((lane >> 3) & 1) * 8;
                const unsigned arsw = ((unsigned)((arow >> 1) & 3)) << 4;
                const int bn_l = (lane & 7) + (lane >> 4) * 8;
                const int bkb_l = ((lane >> 3) & 1) * 16;
                const unsigned abase = AB + (unsigned)((c & 1)*16384);
#pragma unroll
                for (int kk = 0; kk < 2; kk++) {
                    unsigned akb = (unsigned)(kk*32 + (lane >> 4) * 16);
                    unsigned aoff = (unsigned)(arow*64) + (akb ^ arsw);
                    unsigned ah[4], al[4];
                    ldsm4(ah, abase + aoff);
                    ldsm4(al, abase + 8192 + aoff);
                    const int bkb = c*64 + kk*32 + bkb_l;
#pragma unroll
                    for (int g = 0; g < 4; g++) {
                        int bn = ch*64 + g*16 + bn_l;
                        unsigned boff = (unsigned)(bn*768) +
                                        ((unsigned)bkb ^ ((unsigned)(bn & 7) << 4));
                        unsigned bh[4], bl[4];
                        ldsm4(bh, smb + boff);
                        ldsm4(bl, smb + K3_BL + boff);
#pragma unroll
                        for (int s = 0; s < 2; s++) {
                            mma16816(acc[g][s], ah, bh[s*2], bh[s*2+1]);
                            mma16816(acc[g][s], ah, bl[s*2], bl[s*2+1]);
                            mma16816(acc[g][s], al, bh[s*2], bh[s*2+1]);
                        }
                    }
                }
            }
            __syncthreads();
        }

        {
            const size_t rlo = rbase + wrow*16 + (lane >> 2);
            const size_t rhi = rlo + 8;
#pragma unroll
            for (int g = 0; g < 4; g++)
#pragma unroll
                for (int s = 0; s < 2; s++) {
                    int c = ch*64 + g*16 + s*8 + (lane & 3)*2;
                    float2 bi = *(const float2*)(biou + jb + c);
                    *(float2*)(g_IOU + rlo*384 + jb + c) =
                        make_float2(acc[g][s][0] + bi.x, acc[g][s][1] + bi.y);
                    *(float2*)(g_IOU + rhi*384 + jb + c) =
                        make_float2(acc[g][s][2] + bi.x, acc[g][s][3] + bi.y);
                }
        }
    }
}

// ---------------- K3b: gates -> out ----------------
__global__ void k3b(float* __restrict__ out) {
    int idx = blockIdx.x * blockDim.x + threadIdx.x;
    if (idx >= NN*32) return;
    int n = idx >> 5;
    int j = (idx & 31) * 4;
    const float* r = g_IOU + (size_t)n * 384;
    float4 iv = *(const float4*)(r + j);
    float4 ov = *(const float4*)(r + 128 + j);
    float4 uv = *(const float4*)(r + 256 + j);
    float4 cr = *(const float4*)(g_cred + (size_t)n*128 + j);
    float4 hc, cc;
    {
        float ig, og, ug, c, h;
        ig = 1.f/(1.f+expf(-iv.x)); og = 1.f/(1.f+expf(-ov.x)); ug = tanhf(uv.x);
        c = ig*ug + cr.x; h = og*tanhf(c); hc.x = h; cc.x = c;
        ig = 1.f/(1.f+expf(-iv.y)); og = 1.f/(1.f+expf(-ov.y)); ug = tanhf(uv.y);
        c = ig*ug + cr.y; h = og*tanhf(c); hc.y = h; cc.y = c;
        ig = 1.f/(1.f+expf(-iv.z)); og = 1.f/(1.f+expf(-ov.z)); ug = tanhf(uv.z);
        c = ig*ug + cr.z; h = og*tanhf(c); hc.z = h; cc.z = c;
        ig = 1.f/(1.f+expf(-iv.w)); og = 1.f/(1.f+expf(-ov.w)); ug = tanhf(uv.w);
        c = ig*ug + cr.w; h = og*tanhf(c); hc.w = h; cc.w = c;
    }
    *(float4*)(out + (size_t)n*128 + j) = hc;
    *(float4*)(out + (size_t)NN*128 + (size_t)n*128 + j) = cc;
}

// ---------------- launcher ----------------
extern "C" void kernel_launch(void* const* d_in, const int* in_sizes, int n_in,
                              void* d_out, int out_size) {
    const float* x      = (const float*)d_in[0];
    const float* h_mail = (const float*)d_in[1];
    const float* c_mail = (const float*)d_in[2];
    const float* Wiou   = (const float*)d_in[3];
    const float* Uiou   = (const float*)d_in[4];
    const float* biou   = (const float*)d_in[5];
    const float* Of     = (const float*)d_in[6];
    const float* Zf     = (const float*)d_in[7];
    const float* Qf     = (const float*)d_in[8];
    const float* Kf     = (const float*)d_in[9];
    const float* vf     = (const float*)d_in[10];
    const float* Wa     = (const float*)d_in[11];
    const float* Wd     = (const float*)d_in[12];
    const float* Vf     = (const float*)d_in[13];
    const int*   etype  = (const int*)d_in[14];
    float* out = (float*)d_out;

    cudaFuncSetAttribute(k2,  cudaFuncAttributeMaxDynamicSharedMemorySize, K2_SMEM);
    cudaFuncSetAttribute(k3a, cudaFuncAttributeMaxDynamicSharedMemorySize, K3_SMEM);

    k1a<<<128, 256>>>(Wa, Wd, vf);
    k1b<<<577, 256>>>(Uiou, Wiou, Qf, Vf);
    k1c<<<6250, 256>>>(x);
    k2<<<148, 512, K2_SMEM>>>(h_mail, c_mail, Kf, Vf, Of, Zf, etype);
    k3a<<<dim3(3, 49), 512, K3_SMEM>>>(biou);
    k3b<<<6250, 256>>>(out);
}

// round 15
// speedup vs baseline: 1.1052x; 1.1052x over previous
#include <cuda_runtime.h>
#include <cuda_bf16.h>
#include <math.h>

#define NN 50000
#define HH 128
#define NPAD 50048            // 391*128, padded rows (zero-init)
#define TN 16                 // nodes per tile (16*8 = 128 rows)
#define NTILES (NN/TN)        // 3125

// ---------------- scratch (__device__ globals; zero-initialized) ----------------
__device__ float g_T[2*128*128];              // Q0 = vf@Wd | Q1 = vf@Wa
__device__ float g_G[384*384];                // [Q0@U0 ; Q1@U1 ; Wiou]
__device__ float g_qv[128];                   // Qf @ Vf
__device__ float g_px[NN];                    // x . qv  (per node)
__device__ __nv_bfloat16 g_Zh[(size_t)NPAD*384];  // Z hi (bf16 split)
__device__ __nv_bfloat16 g_Zl[(size_t)NPAD*384];  // Z lo
__device__ float g_IOU[(size_t)NPAD*384];
__device__ float g_cred[(size_t)NN*128];

// ================= helpers =================
__device__ __forceinline__ unsigned smem_u32(const void* p) {
    unsigned a;
    asm("{ .reg .u64 t; cvta.to.shared.u64 t, %1; cvt.u32.u64 %0, t; }" : "=r"(a) : "l"(p));
    return a;
}

__device__ __forceinline__ void ldsm4(unsigned r[4], unsigned addr) {
    asm volatile("ldmatrix.sync.aligned.m8n8.x4.shared.b16 {%0,%1,%2,%3}, [%4];"
                 : "=r"(r[0]), "=r"(r[1]), "=r"(r[2]), "=r"(r[3]) : "r"(addr));
}

__device__ __forceinline__ void mma16816(float c[4], const unsigned a[4],
                                         unsigned b0, unsigned b1) {
    asm volatile("mma.sync.aligned.m16n8k16.row.col.f32.bf16.bf16.f32 "
                 "{%0,%1,%2,%3}, {%4,%5,%6,%7}, {%8,%9}, {%0,%1,%2,%3};"
                 : "+f"(c[0]), "+f"(c[1]), "+f"(c[2]), "+f"(c[3])
                 : "r"(a[0]), "r"(a[1]), "r"(a[2]), "r"(a[3]), "r"(b0), "r"(b1));
}

#define CP_ASYNC16(dst, src) \
    asm volatile("cp.async.cg.shared.global [%0], [%1], 16;" :: "r"(dst), "l"(src) : "memory")
#define CP_COMMIT()  asm volatile("cp.async.commit_group;" ::: "memory")
#define CP_WAIT1()   asm volatile("cp.async.wait_group 1;" ::: "memory")
#define CP_WAIT0()   asm volatile("cp.async.wait_group 0;" ::: "memory")

// fp32 -> bf16 hi/lo split, 2 elements packed per word
__device__ __forceinline__ void split2(float a, float b, unsigned& hi, unsigned& lo) {
    __nv_bfloat16 ha = __float2bfloat16_rn(a);
    __nv_bfloat16 hb = __float2bfloat16_rn(b);
    __nv_bfloat16 la = __float2bfloat16_rn(a - __bfloat162float(ha));
    __nv_bfloat16 lb = __float2bfloat16_rn(b - __bfloat162float(hb));
    hi = ((unsigned)__bfloat16_as_ushort(hb) << 16) | (unsigned)__bfloat16_as_ushort(ha);
    lo = ((unsigned)__bfloat16_as_ushort(lb) << 16) | (unsigned)__bfloat16_as_ushort(la);
}

__device__ __forceinline__ float shflr(float v, int m) {
    return __shfl_xor_sync(0xffffffffu, v, m);
}

// ---------------- K1a: Q0 = vf@Wd, Q1 = vf@Wa (128x128 each) ----------------
__global__ void k1a(const float* __restrict__ Wa, const float* __restrict__ Wd,
                    const float* __restrict__ vf) {
    int idx = blockIdx.x * blockDim.x + threadIdx.x;
    if (idx >= 2*128*128) return;
    int which = idx >> 14;
    int rem   = idx & 16383;
    int m = rem >> 7, j = rem & 127;
    const float* W = which ? Wa : Wd;
    float s = 0.f;
#pragma unroll 8
    for (int z = 0; z < 128; z++) s += vf[m*128+z] * W[z*128+j];
    g_T[idx] = s;
}

// ---------------- K1b: G = [Q0@U0 ; Q1@U1 ; Wiou]; qv = Qf@Vf ----------------
__global__ void k1b(const float* __restrict__ Uiou, const float* __restrict__ Wiou,
                    const float* __restrict__ Qf, const float* __restrict__ Vf) {
    int idx = blockIdx.x * blockDim.x + threadIdx.x;
    if (idx < 2*128*384) {
        int which = idx / (128*384);
        int rem   = idx - which*(128*384);
        int m = rem / 384, j = rem - m*384;
        const float* Q = g_T + which*(128*128);
        const float* U = Uiou + which*(128*384);
        float s = 0.f;
#pragma unroll 8
        for (int z = 0; z < 128; z++) s += Q[m*128+z] * U[z*384+j];
        g_G[idx] = s;
    } else if (idx < 3*128*384) {
        int rem = idx - 2*128*384;
        g_G[idx] = Wiou[rem];
    } else if (idx < 3*128*384 + 128) {
        int m = idx - 3*128*384;
        float s = 0.f;
#pragma unroll 8
        for (int j = 0; j < 128; j++) s += Qf[m*128+j] * Vf[j];
        g_qv[m] = s;
    }
}

// ---------------- K1c: px = x . qv ; x -> Zh/Zl cols [256,384) ----------------
__global__ void k1c(const float* __restrict__ x) {
    int idx = blockIdx.x * blockDim.x + threadIdx.x;   // NN*32
    if (idx >= NN*32) return;
    int n = idx >> 5;
    int j = (idx & 31) * 4;
    float4 v = *(const float4*)(x + (size_t)n*128 + j);
    unsigned h0, l0, h1, l1;
    split2(v.x, v.y, h0, l0);
    split2(v.z, v.w, h1, l1);
    size_t o = (size_t)n*384 + 256 + j;
    *(unsigned*)(g_Zh + o)     = h0;
    *(unsigned*)(g_Zh + o + 2) = h1;
    *(unsigned*)(g_Zl + o)     = l0;
    *(unsigned*)(g_Zl + o + 2) = l1;
    float p = v.x*g_qv[j] + v.y*g_qv[j+1] + v.z*g_qv[j+2] + v.w*g_qv[j+3];
#pragma unroll
    for (int m = 1; m < 32; m <<= 1) p += shflr(p, m);
    if ((idx & 31) == 0) g_px[n] = p;
}

// ---------------- K2 (fused; cp.async fp32 A + in-register split; R12 warp map) ----------------
// Weights resident: Kh Kl Zh Zl Dh Dl (6 x 32KB). A: 2 buffers x 16KB fp32 (32-k chunks).
// A layout: rows 128B fp32, 16B-seg XOR swizzle ((row&7)<<4). pb aliases buf0 (post-MMA only).
#define K2_AB   196608
#define K2_SMEM 229376
__global__ void __launch_bounds__(512, 1)
k2(const float* __restrict__ hmail, const float* __restrict__ cmail,
   const float* __restrict__ Kf, const float* __restrict__ Vf,
   const float* __restrict__ Of, const float* __restrict__ Zf,
   const int* __restrict__ etype) {
    extern __shared__ char smc[];
    const unsigned smb = smem_u32(smc);
    const int tid = threadIdx.x, wid = tid >> 5, lane = tid & 31;
    const int wrow = wid & 7, ch = wid >> 3;        // row stripe, col half
    float* pb = (float*)(smc + K2_AB);              // alias buf0 (post-MMA use only)

    // weight prep: B[n][k] = W[k][n]; bf16 hi/lo; row stride 256B, XOR swizzle
    for (int idx = tid; idx < 128*128; idx += 512) {
        int n = idx & 127, k = idx >> 7;
        unsigned off = (unsigned)(n*256 + ((2*k) ^ ((n & 7) << 4)));
        float kf = Kf[k*128 + n];
        __nv_bfloat16 kh = __float2bfloat16_rn(kf);
        __nv_bfloat16 kl = __float2bfloat16_rn(kf - __bfloat162float(kh));
        *(__nv_bfloat16*)(smc + 0*32768 + off) = kh;
        *(__nv_bfloat16*)(smc + 1*32768 + off) = kl;
        float zf = Zf[k*128 + n];
        float d  = Of[k*128 + n] - zf;
        __nv_bfloat16 zh = __float2bfloat16_rn(zf);
        __nv_bfloat16 zl = __float2bfloat16_rn(zf - __bfloat162float(zh));
        __nv_bfloat16 dh = __float2bfloat16_rn(d);
        __nv_bfloat16 dl = __float2bfloat16_rn(d - __bfloat162float(dh));
        *(__nv_bfloat16*)(smc + 2*32768 + off) = zh;
        *(__nv_bfloat16*)(smc + 3*32768 + off) = zl;
        *(__nv_bfloat16*)(smc + 4*32768 + off) = dh;
        *(__nv_bfloat16*)(smc + 5*32768 + off) = dl;
    }
    __syncthreads();

    // cp.async fill mapping: thread -> (row, segs tid&3 and +4); 2 x 16B per thread
    const int crow = tid >> 2, cs0 = tid & 3;
    const unsigned crsw = (unsigned)((crow & 7) << 4);
    const unsigned cd0 = (unsigned)(crow*128) + (((unsigned)cs0*16) ^ crsw);
    const unsigned cd1 = (unsigned)(crow*128) + (((unsigned)(cs0+4)*16) ^ crsw);

    for (int tile = blockIdx.x; tile < NTILES; tile += gridDim.x) {
        const size_t rbase = (size_t)tile * 128;

        const unsigned mlo = (etype[rbase + wrow*16 + (lane >> 2)]     != 0) ? 0xffffffffu : 0u;
        const unsigned mhi = (etype[rbase + wrow*16 + 8 + (lane >> 2)] != 0) ? 0xffffffffu : 0u;

        float acck[4][2][4], accf[4][2][4];
#pragma unroll
        for (int g = 0; g < 4; g++)
#pragma unroll
            for (int s = 0; s < 2; s++)
#pragma unroll
                for (int q = 0; q < 4; q++) { acck[g][s][q] = 0.f; accf[g][s][q] = 0.f; }

        // prologue: chunk 0 -> buf0
        {
            const float* src = hmail + (rbase + crow)*128;
            CP_ASYNC16(smb + K2_AB + cd0, (const void*)(src + cs0*4));
            CP_ASYNC16(smb + K2_AB + cd1, (const void*)(src + (cs0+4)*4));
            CP_COMMIT();
        }

        for (int c = 0; c < 4; c++) {
            if (c < 3) {    // fill chunk c+1 into the other buffer
                const float* src = hmail + (rbase + crow)*128 + (c+1)*32;
                unsigned dst = smb + K2_AB + (unsigned)(((c+1) & 1)*16384);
                CP_ASYNC16(dst + cd0, (const void*)(src + cs0*4));
                CP_ASYNC16(dst + cd1, (const void*)(src + (cs0+4)*4));
                CP_COMMIT();
                CP_WAIT1();
            } else {
                CP_WAIT0();
            }
            __syncthreads();
            // ---- MMA on chunk c (32 k = 2 kk steps); A loaded as fp32 + reg split ----
            {
                const int abuf = K2_AB + (c & 1)*16384;
                const int rlo = wrow*16 + (lane >> 2);
                const int rhi = rlo + 8;
                const unsigned swlo = (unsigned)((rlo & 7) << 4);
                const unsigned swhi = (unsigned)((rhi & 7) << 4);
                const int bn_l = (lane & 7) + (lane >> 4) * 8;
                const int bkb_l = ((lane >> 3) & 1) * 16;
#pragma unroll
                for (int kk = 0; kk < 2; kk++) {
                    // fragment fp32 loads: k bytes = kk*64 + (lane&3)*8, and +32 for k+8
                    const unsigned kb = (unsigned)(kk*64 + (lane & 3)*8);
                    float2 v0 = *(const float2*)(smc + abuf + rlo*128 + (kb ^ swlo));
                    float2 v1 = *(const float2*)(smc + abuf + rhi*128 + (kb ^ swhi));
                    float2 v2 = *(const float2*)(smc + abuf + rlo*128 + ((kb + 32) ^ swlo));
                    float2 v3 = *(const float2*)(smc + abuf + rhi*128 + ((kb + 32) ^ swhi));
                    unsigned ah[4], al[4], aeh[4], ael[4];
                    split2(v0.x, v0.y, ah[0], al[0]);
                    split2(v1.x, v1.y, ah[1], al[1]);
                    split2(v2.x, v2.y, ah[2], al[2]);
                    split2(v3.x, v3.y, ah[3], al[3]);
                    aeh[0] = ah[0] & mlo; aeh[1] = ah[1] & mhi;
                    aeh[2] = ah[2] & mlo; aeh[3] = ah[3] & mhi;
                    ael[0] = al[0] & mlo; ael[1] = al[1] & mhi;
                    ael[2] = al[2] & mlo; ael[3] = al[3] & mhi;
                    const int bkb = c*64 + kk*32 + bkb_l;
#pragma unroll
                    for (int g = 0; g < 4; g++) {
                        int bn = ch*64 + g*16 + bn_l;
                        unsigned boff = (unsigned)(bn*256) +
                                        ((unsigned)bkb ^ ((unsigned)(bn & 7) << 4));
                        unsigned kh[4], kl[4], zh[4], zl[4], dh[4], dl[4];
                        ldsm4(kh, smb + 0*32768 + boff);
                        ldsm4(kl, smb + 1*32768 + boff);
                        ldsm4(zh, smb + 2*32768 + boff);
                        ldsm4(zl, smb + 3*32768 + boff);
                        ldsm4(dh, smb + 4*32768 + boff);
                        ldsm4(dl, smb + 5*32768 + boff);
#pragma unroll
                        for (int s = 0; s < 2; s++) {
                            mma16816(acck[g][s], ah,  kh[s*2], kh[s*2+1]);
                            mma16816(acck[g][s], ah,  kl[s*2], kl[s*2+1]);
                            mma16816(acck[g][s], al,  kh[s*2], kh[s*2+1]);
                            mma16816(accf[g][s], ah,  zh[s*2], zh[s*2+1]);
                            mma16816(accf[g][s], ah,  zl[s*2], zl[s*2+1]);
                            mma16816(accf[g][s], al,  zh[s*2], zh[s*2+1]);
                            mma16816(accf[g][s], aeh, dh[s*2], dh[s*2+1]);
                            mma16816(accf[g][s], aeh, dl[s*2], dl[s*2+1]);
                            mma16816(accf[g][s], ael, dh[s*2], dh[s*2+1]);
                        }
                    }
                }
            }
            __syncthreads();   // all warps done with buf (c&1) before its refill
        }

        const int rlo = wrow*16 + (lane >> 2);     // local mail row (node0)
        const int rhi = rlo + 8;                   // node1
        const int node0 = tile*TN + wrow*2, node1 = node0 + 1;

        // ---- f epilogue: f = sigmoid(accf); c_red = sum over 8 mail rows ----
#pragma unroll
        for (int g = 0; g < 4; g++)
#pragma unroll
            for (int s = 0; s < 2; s++) {
                int col = ch*64 + g*16 + s*8 + (lane & 3)*2;
                float2 c0 = *(const float2*)(cmail + (rbase + rlo)*128 + col);
                float2 c1 = *(const float2*)(cmail + (rbase + rhi)*128 + col);
                float v0 = c0.x / (1.f + expf(-accf[g][s][0]));
                float v1 = c0.y / (1.f + expf(-accf[g][s][1]));
                float v2 = c1.x / (1.f + expf(-accf[g][s][2]));
                float v3 = c1.y / (1.f + expf(-accf[g][s][3]));
#pragma unroll
                for (int m = 4; m < 32; m <<= 1) {
                    v0 += shflr(v0, m); v1 += shflr(v1, m);
                    v2 += shflr(v2, m); v3 += shflr(v3, m);
                }
                if (lane < 4) {
                    int c = ch*64 + g*16 + s*8 + lane*2;
                    *(float2*)(g_cred + (size_t)node0*128 + c) = make_float2(v0, v1);
                } else if (lane < 8) {
                    int c = ch*64 + g*16 + s*8 + (lane - 4)*2;
                    *(float2*)(g_cred + (size_t)node1*128 + c) = make_float2(v2, v3);
                }
            }

        // ---- k epilogue: softmax over mails, weighted sums -> g_Zh/g_Zl ----
        float plo = 0.f, phi = 0.f;
#pragma unroll
        for (int g = 0; g < 4; g++)
#pragma unroll
            for (int s = 0; s < 2; s++) {
                int c = ch*64 + g*16 + s*8 + (lane & 3)*2;
                float vf0 = __ldg(Vf + c), vf1 = __ldg(Vf + c + 1);
                plo += acck[g][s][0]*vf0 + acck[g][s][1]*vf1;
                phi += acck[g][s][2]*vf0 + acck[g][s][3]*vf1;
            }
        plo += shflr(plo, 1); plo += shflr(plo, 2);
        phi += shflr(phi, 1); phi += shflr(phi, 2);
        if ((lane & 3) == 0) {
            pb[ch*128 + rlo] = plo;
            pb[ch*128 + rhi] = phi;
        }
        __syncthreads();
        float p_lo = pb[rlo] + pb[128 + rlo];
        float p_hi = pb[rhi] + pb[128 + rhi];

        float e_lo = (float)etype[rbase + rlo];
        float e_hi = (float)etype[rbase + rhi];
        float sc_lo = tanhf(g_px[node0] + p_lo);
        float sc_hi = tanhf(g_px[node1] + p_hi);

        float mx0 = sc_lo, mx1 = sc_hi, se0, se1, sm0 = e_lo, sm1 = e_hi;
#pragma unroll
        for (int m = 4; m < 32; m <<= 1) {
            mx0 = fmaxf(mx0, shflr(mx0, m));
            mx1 = fmaxf(mx1, shflr(mx1, m));
            sm0 += shflr(sm0, m);
            sm1 += shflr(sm1, m);
        }
        float ex0 = expf(sc_lo - mx0), ex1 = expf(sc_hi - mx1);
        se0 = ex0; se1 = ex1;
#pragma unroll
        for (int m = 4; m < 32; m <<= 1) { se0 += shflr(se0, m); se1 += shflr(se1, m); }
        float w0 = ex0 / se0, w1 = ex1 / se1;
        float mod0 = sm0 * 0.125f, mod1 = sm1 * 0.125f;
        float c1_lo = w0 * (1.f - mod0) * e_lo;
        float c0_lo = w0 * mod0 * (1.f - e_lo);
        float c1_hi = w1 * (1.f - mod1) * e_hi;
        float c0_hi = w1 * mod1 * (1.f - e_hi);

#pragma unroll
        for (int g = 0; g < 4; g++)
#pragma unroll
            for (int s = 0; s < 2; s++) {
                float b00 = c0_lo*acck[g][s][0], b01 = c0_lo*acck[g][s][1];
                float a00 = c1_lo*acck[g][s][0], a01 = c1_lo*acck[g][s][1];
                float b10 = c0_hi*acck[g][s][2], b11 = c0_hi*acck[g][s][3];
                float a10 = c1_hi*acck[g][s][2], a11 = c1_hi*acck[g][s][3];
#pragma unroll
                for (int m = 4; m < 32; m <<= 1) {
                    b00 += shflr(b00, m); b01 += shflr(b01, m);
                    a00 += shflr(a00, m); a01 += shflr(a01, m);
                    b10 += shflr(b10, m); b11 += shflr(b11, m);
                    a10 += shflr(a10, m); a11 += shflr(a11, m);
                }
                if (lane < 4) {
                    int c = ch*64 + g*16 + s*8 + lane*2;
                    size_t ro = (size_t)node0 * 384;
                    unsigned hi, lo;
                    split2(b00, b01, hi, lo);
                    *(unsigned*)(g_Zh + ro + c) = hi;
                    *(unsigned*)(g_Zl + ro + c) = lo;
                    split2(a00, a01, hi, lo);
                    *(unsigned*)(g_Zh + ro + 128 + c) = hi;
                    *(unsigned*)(g_Zl + ro + 128 + c) = lo;
                } else if (lane < 8) {
                    int c = ch*64 + g*16 + s*8 + (lane - 4)*2;
                    size_t ro = (size_t)node1 * 384;
                    unsigned hi, lo;
                    split2(b10, b11, hi, lo);
                    *(unsigned*)(g_Zh + ro + c) = hi;
                    *(unsigned*)(g_Zl + ro + c) = lo;
                    split2(a10, a11, hi, lo);
                    *(unsigned*)(g_Zh + ro + 128 + c) = hi;
                    *(unsigned*)(g_Zl + ro + 128 + c) = lo;
                }
            }
        __syncthreads();   // pb (aliases buf0) fully read before next tile's prologue
    }
}

// ---------------- K3a (mma.sync bf16, 3-term, cp.async double-buffered A) ----------------
// SMEM: Bh 96K | Bl 96K | A bufs 2 x (Ah 8K + Al 8K) = 229376 B
#define K3_BL   98304
#define K3_AB   196608
#define K3_SMEM 229376
__global__ void __launch_bounds__(512, 1)
k3a(const float* __restrict__ biou) {
    extern __shared__ char smc[];
    const unsigned smb = smem_u32(smc);
    const int tid = threadIdx.x, wid = tid >> 5, lane = tid & 31;
    const int wrow = wid & 7, ch = wid >> 3;
    const int jb = blockIdx.x * 128;           // output col block
    const unsigned AB = smb + K3_AB;

    // B fill: B[n][k] = G[k][jb+n], bf16 hi/lo, row stride 768B, XOR swizzle
    for (int idx = tid; idx < 128*384; idx += 512) {
        int k = idx % 384, n = idx / 384;
        float v = g_G[k*384 + jb + n];
        __nv_bfloat16 bh = __float2bfloat16_rn(v);
        __nv_bfloat16 bl = __float2bfloat16_rn(v - __bfloat162float(bh));
        unsigned off = (unsigned)(n*768 + ((2*k) ^ ((n & 7) << 4)));
        *(__nv_bfloat16*)(smc + off)          = bh;
        *(__nv_bfloat16*)(smc + K3_BL + off)  = bl;
    }
    __syncthreads();

    const int crow = tid >> 2, cseg = tid & 3;
    const unsigned csw = ((unsigned)((crow >> 1) & 3)) << 4;
    const unsigned cdo = (unsigned)(crow*64) + (((unsigned)cseg*16) ^ csw);

    for (int rt = blockIdx.y; rt < 391; rt += gridDim.y) {
        const size_t rbase = (size_t)rt * 128;

        {
            const size_t go = (rbase + crow)*384 + cseg*8;
            CP_ASYNC16(AB + cdo,        (const void*)(g_Zh + go));
            CP_ASYNC16(AB + 8192 + cdo, (const void*)(g_Zl + go));
            CP_COMMIT();
        }

        float acc[4][2][4];
#pragma unroll
        for (int g = 0; g < 4; g++)
#pragma unroll
            for (int s = 0; s < 2; s++)
#pragma unroll
                for (int q = 0; q < 4; q++) acc[g][s][q] = 0.f;

        for (int c = 0; c < 12; c++) {
            if (c < 11) {
                const size_t go = (rbase + crow)*384 + (c+1)*32 + cseg*8;
                unsigned dst = AB + (unsigned)(((c+1) & 1)*16384) + cdo;
                CP_ASYNC16(dst,        (const void*)(g_Zh + go));
                CP_ASYNC16(dst + 8192, (const void*)(g_Zl + go));
                CP_COMMIT();
                CP_WAIT1();
            } else {
                CP_WAIT0();
            }
            __syncthreads();
            {
                const int arow = wrow*16 + (lane & 7) + ((lane >> 3) & 1) * 8;
                const unsigned arsw = ((unsigned)((arow >> 1) & 3)) << 4;
                const int bn_l = (lane & 7) + (lane >> 4) * 8;
                const int bkb_l = ((lane >> 3) & 1) * 16;
                const unsigned abase = AB + (unsigned)((c & 1)*16384);
#pragma unroll
                for (int kk = 0; kk < 2; kk++) {
                    unsigned akb = (unsigned)(kk*32 + (lane >> 4) * 16);
                    unsigned aoff = (unsigned)(arow*64) + (akb ^ arsw);
                    unsigned ah[4], al[4];
                    ldsm4(ah, abase + aoff);
                    ldsm4(al, abase + 8192 + aoff);
                    const int bkb = c*64 + kk*32 + bkb_l;
#pragma unroll
                    for (int g = 0; g < 4; g++) {
                        int bn = ch*64 + g*16 + bn_l;
                        unsigned boff = (unsigned)(bn*768) +
                                        ((unsigned)bkb ^ ((unsigned)(bn & 7) << 4));
                        unsigned bh[4], bl[4];
                        ldsm4(bh, smb + boff);
                        ldsm4(bl, smb + K3_BL + boff);
#pragma unroll
                        for (int s = 0; s < 2; s++) {
                            mma16816(acc[g][s], ah, bh[s*2], bh[s*2+1]);
                            mma16816(acc[g][s], ah, bl[s*2], bl[s*2+1]);
                            mma16816(acc[g][s], al, bh[s*2], bh[s*2+1]);
                        }
                    }
                }
            }
            __syncthreads();
        }

        {
            const size_t rlo = rbase + wrow*16 + (lane >> 2);
            const size_t rhi = rlo + 8;
#pragma unroll
            for (int g = 0; g < 4; g++)
#pragma unroll
                for (int s = 0; s < 2; s++) {
                    int c = ch*64 + g*16 + s*8 + (lane & 3)*2;
                    float2 bi = *(const float2*)(biou + jb + c);
                    *(float2*)(g_IOU + rlo*384 + jb + c) =
                        make_float2(acc[g][s][0] + bi.x, acc[g][s][1] + bi.y);
                    *(float2*)(g_IOU + rhi*384 + jb + c) =
                        make_float2(acc[g][s][2] + bi.x, acc[g][s][3] + bi.y);
                }
        }
    }
}

// ---------------- K3b: gates -> out ----------------
__global__ void k3b(float* __restrict__ out) {
    int idx = blockIdx.x * blockDim.x + threadIdx.x;
    if (idx >= NN*32) return;
    int n = idx >> 5;
    int j = (idx & 31) * 4;
    const float* r = g_IOU + (size_t)n * 384;
    float4 iv = *(const float4*)(r + j);
    float4 ov = *(const float4*)(r + 128 + j);
    float4 uv = *(const float4*)(r + 256 + j);
    float4 cr = *(const float4*)(g_cred + (size_t)n*128 + j);
    float4 hc, cc;
    {
        float ig, og, ug, c, h;
        ig = 1.f/(1.f+expf(-iv.x)); og = 1.f/(1.f+expf(-ov.x)); ug = tanhf(uv.x);
        c = ig*ug + cr.x; h = og*tanhf(c); hc.x = h; cc.x = c;
        ig = 1.f/(1.f+expf(-iv.y)); og = 1.f/(1.f+expf(-ov.y)); ug = tanhf(uv.y);
        c = ig*ug + cr.y; h = og*tanhf(c); hc.y = h; cc.y = c;
        ig = 1.f/(1.f+expf(-iv.z)); og = 1.f/(1.f+expf(-ov.z)); ug = tanhf(uv.z);
        c = ig*ug + cr.z; h = og*tanhf(c); hc.z = h; cc.z = c;
        ig = 1.f/(1.f+expf(-iv.w)); og = 1.f/(1.f+expf(-ov.w)); ug = tanhf(uv.w);
        c = ig*ug + cr.w; h = og*tanhf(c); hc.w = h; cc.w = c;
    }
    *(float4*)(out + (size_t)n*128 + j) = hc;
    *(float4*)(out + (size_t)NN*128 + (size_t)n*128 + j) = cc;
}

// ---------------- launcher ----------------
extern "C" void kernel_launch(void* const* d_in, const int* in_sizes, int n_in,
                              void* d_out, int out_size) {
    const float* x      = (const float*)d_in[0];
    const float* h_mail = (const float*)d_in[1];
    const float* c_mail = (const float*)d_in[2];
    const float* Wiou   = (const float*)d_in[3];
    const float* Uiou   = (const float*)d_in[4];
    const float* biou   = (const float*)d_in[5];
    const float* Of     = (const float*)d_in[6];
    const float* Zf     = (const float*)d_in[7];
    const float* Qf     = (const float*)d_in[8];
    const float* Kf     = (const float*)d_in[9];
    const float* vf     = (const float*)d_in[10];
    const float* Wa     = (const float*)d_in[11];
    const float* Wd     = (const float*)d_in[12];
    const float* Vf     = (const float*)d_in[13];
    const int*   etype  = (const int*)d_in[14];
    float* out = (float*)d_out;

    cudaFuncSetAttribute(k2,  cudaFuncAttributeMaxDynamicSharedMemorySize, K2_SMEM);
    cudaFuncSetAttribute(k3a, cudaFuncAttributeMaxDynamicSharedMemorySize, K3_SMEM);

    k1a<<<128, 256>>>(Wa, Wd, vf);
    k1b<<<577, 256>>>(Uiou, Wiou, Qf, Vf);
    k1c<<<6250, 256>>>(x);
    k2<<<148, 512, K2_SMEM>>>(h_mail, c_mail, Kf, Vf, Of, Zf, etype);
    k3a<<<dim3(3, 49), 512, K3_SMEM>>>(biou);
    k3b<<<6250, 256>>>(out);
}

// round 17
// speedup vs baseline: 1.3048x; 1.1806x over previous
#include <cuda_runtime.h>
#include <cuda_bf16.h>
#include <math.h>

#define NN 50000
#define HH 128
#define NPAD 50048            // 391*128, padded rows (zero-init)
#define TN 16                 // nodes per tile (16*8 = 128 rows)
#define NTILES (NN/TN)        // 3125

// ---------------- scratch (__device__ globals; zero-initialized) ----------------
__device__ float g_T[2*128*128];              // Q0 = vf@Wd | Q1 = vf@Wa
__device__ float g_G[384*384];                // [Q0@U0 ; Q1@U1 ; Wiou]
__device__ float g_Gp[384*384];               // [Kf@(Q0@U0) ; Kf@(Q1@U1) ; Wiou]
__device__ float g_qv[128];                   // Qf @ Vf
__device__ float g_kv[128];                   // Kf @ Vf
__device__ float g_px[NN];                    // x . qv  (per node)
__device__ __nv_bfloat16 g_Zh[(size_t)NPAD*384];  // [u0|u1|x] hi (bf16 split)
__device__ __nv_bfloat16 g_Zl[(size_t)NPAD*384];  // lo
__device__ float g_IOU[(size_t)NPAD*384];
__device__ float g_cred[(size_t)NN*128];

// ================= helpers =================
__device__ __forceinline__ unsigned smem_u32(const void* p) {
    unsigned a;
    asm("{ .reg .u64 t; cvta.to.shared.u64 t, %1; cvt.u32.u64 %0, t; }" : "=r"(a) : "l"(p));
    return a;
}

__device__ __forceinline__ void ldsm4(unsigned r[4], unsigned addr) {
    asm volatile("ldmatrix.sync.aligned.m8n8.x4.shared.b16 {%0,%1,%2,%3}, [%4];"
                 : "=r"(r[0]), "=r"(r[1]), "=r"(r[2]), "=r"(r[3]) : "r"(addr));
}

__device__ __forceinline__ void mma16816(float c[4], const unsigned a[4],
                                         unsigned b0, unsigned b1) {
    asm volatile("mma.sync.aligned.m16n8k16.row.col.f32.bf16.bf16.f32 "
                 "{%0,%1,%2,%3}, {%4,%5,%6,%7}, {%8,%9}, {%0,%1,%2,%3};"
                 : "+f"(c[0]), "+f"(c[1]), "+f"(c[2]), "+f"(c[3])
                 : "r"(a[0]), "r"(a[1]), "r"(a[2]), "r"(a[3]), "r"(b0), "r"(b1));
}

#define CP_ASYNC16(dst, src) \
    asm volatile("cp.async.cg.shared.global [%0], [%1], 16;" :: "r"(dst), "l"(src) : "memory")
#define CP_COMMIT()  asm volatile("cp.async.commit_group;" ::: "memory")
#define CP_WAIT1()   asm volatile("cp.async.wait_group 1;" ::: "memory")
#define CP_WAIT0()   asm volatile("cp.async.wait_group 0;" ::: "memory")

// fp32 -> bf16 hi/lo split, 2 elements packed per word
__device__ __forceinline__ void split2(float a, float b, unsigned& hi, unsigned& lo) {
    __nv_bfloat16 ha = __float2bfloat16_rn(a);
    __nv_bfloat16 hb = __float2bfloat16_rn(b);
    __nv_bfloat16 la = __float2bfloat16_rn(a - __bfloat162float(ha));
    __nv_bfloat16 lb = __float2bfloat16_rn(b - __bfloat162float(hb));
    hi = ((unsigned)__bfloat16_as_ushort(hb) << 16) | (unsigned)__bfloat16_as_ushort(ha);
    lo = ((unsigned)__bfloat16_as_ushort(lb) << 16) | (unsigned)__bfloat16_as_ushort(la);
}

__device__ __forceinline__ float shflr(float v, int m) {
    return __shfl_xor_sync(0xffffffffu, v, m);
}

// ---------------- K1a: Q0 = vf@Wd, Q1 = vf@Wa (128x128 each) ----------------
__global__ void k1a(const float* __restrict__ Wa, const float* __restrict__ Wd,
                    const float* __restrict__ vf) {
    int idx = blockIdx.x * blockDim.x + threadIdx.x;
    if (idx >= 2*128*128) return;
    int which = idx >> 14;
    int rem   = idx & 16383;
    int m = rem >> 7, j = rem & 127;
    const float* W = which ? Wa : Wd;
    float s = 0.f;
#pragma unroll 8
    for (int z = 0; z < 128; z++) s += vf[m*128+z] * W[z*128+j];
    g_T[idx] = s;
}

// ---------------- K1b: G = [Q0@U0 ; Q1@U1 ; Wiou]; qv = Qf@Vf; kv = Kf@Vf ----------------
__global__ void k1b(const float* __restrict__ Uiou, const float* __restrict__ Wiou,
                    const float* __restrict__ Qf, const float* __restrict__ Kf,
                    const float* __restrict__ Vf) {
    int idx = blockIdx.x * blockDim.x + threadIdx.x;
    if (idx < 2*128*384) {
        int which = idx / (128*384);
        int rem   = idx - which*(128*384);
        int m = rem / 384, j = rem - m*384;
        const float* Q = g_T + which*(128*128);
        const float* U = Uiou + which*(128*384);
        float s = 0.f;
#pragma unroll 8
        for (int z = 0; z < 128; z++) s += Q[m*128+z] * U[z*384+j];
        g_G[idx] = s;
    } else if (idx < 3*128*384) {
        int rem = idx - 2*128*384;
        g_G[idx] = Wiou[rem];
    } else if (idx < 3*128*384 + 128) {
        int m = idx - 3*128*384;
        float s = 0.f;
#pragma unroll 8
        for (int j = 0; j < 128; j++) s += Qf[m*128+j] * Vf[j];
        g_qv[m] = s;
    } else if (idx < 3*128*384 + 256) {
        int m = idx - 3*128*384 - 128;
        float s = 0.f;
#pragma unroll 8
        for (int j = 0; j < 128; j++) s += Kf[m*128+j] * Vf[j];
        g_kv[m] = s;
    }
}

// ---------------- K1bb: Gp rows [0,256) = Kf @ G[0:256); rows [256,384) copy ----------------
__global__ void k1bb(const float* __restrict__ Kf) {
    int idx = blockIdx.x * blockDim.x + threadIdx.x;
    if (idx >= 3*128*384) return;
    if (idx < 2*128*384) {
        int which = idx / (128*384);
        int rem   = idx - which*(128*384);
        int m = rem / 384, j = rem - m*384;
        const float* T = g_G + which*(128*384);
        float s = 0.f;
#pragma unroll 8
        for (int z = 0; z < 128; z++) s += Kf[m*128+z] * T[z*384+j];
        g_Gp[idx] = s;
    } else {
        g_Gp[idx] = g_G[idx];
    }
}

// ---------------- K1c: px = x . qv ; x -> Zh/Zl cols [256,384) ----------------
__global__ void k1c(const float* __restrict__ x) {
    int idx = blockIdx.x * blockDim.x + threadIdx.x;   // NN*32
    if (idx >= NN*32) return;
    int n = idx >> 5;
    int j = (idx & 31) * 4;
    float4 v = *(const float4*)(x + (size_t)n*128 + j);
    unsigned h0, l0, h1, l1;
    split2(v.x, v.y, h0, l0);
    split2(v.z, v.w, h1, l1);
    size_t o = (size_t)n*384 + 256 + j;
    *(unsigned*)(g_Zh + o)     = h0;
    *(unsigned*)(g_Zh + o + 2) = h1;
    *(unsigned*)(g_Zl + o)     = l0;
    *(unsigned*)(g_Zl + o + 2) = l1;
    float p = v.x*g_qv[j] + v.y*g_qv[j+1] + v.z*g_qv[j+2] + v.w*g_qv[j+3];
#pragma unroll
    for (int m = 1; m < 32; m <<= 1) p += shflr(p, m);
    if ((idx & 31) == 0) g_px[n] = p;
}

// ---------------- K2: f-GEMM only (6 MMA terms) + fp32 p-dots + u-sums ----------------
// Weights resident: Zh Zl Dh Dl (4 x 32KB). A: 2 buffers x 16KB fp32 (32-k chunks).
// kv vector in SMEM. pb (128 floats, per-row p) aliases buf0 (post-MMA use only).
#define K2_AB   131072
#define K2_KV   163840
#define K2_SMEM 164352
__global__ void __launch_bounds__(512, 1)
k2(const float* __restrict__ hmail, const float* __restrict__ cmail,
   const float* __restrict__ Of, const float* __restrict__ Zf,
   const int* __restrict__ etype) {
    extern __shared__ char smc[];
    const unsigned smb = smem_u32(smc);
    const int tid = threadIdx.x, wid = tid >> 5, lane = tid & 31;
    const int wrow = wid & 7, ch = wid >> 3;        // row stripe, col half
    float* pb  = (float*)(smc + K2_AB);             // alias buf0 (post-MMA use only)
    float* kvs = (float*)(smc + K2_KV);

    // weight prep: B[n][k] = W[k][n]; bf16 hi/lo; row stride 256B, XOR swizzle
    for (int idx = tid; idx < 128*128; idx += 512) {
        int n = idx & 127, k = idx >> 7;
        unsigned off = (unsigned)(n*256 + ((2*k) ^ ((n & 7) << 4)));
        float zf = Zf[k*128 + n];
        float d  = Of[k*128 + n] - zf;
        __nv_bfloat16 zh = __float2bfloat16_rn(zf);
        __nv_bfloat16 zl = __float2bfloat16_rn(zf - __bfloat162float(zh));
        __nv_bfloat16 dh = __float2bfloat16_rn(d);
        __nv_bfloat16 dl = __float2bfloat16_rn(d - __bfloat162float(dh));
        *(__nv_bfloat16*)(smc + 0*32768 + off) = zh;
        *(__nv_bfloat16*)(smc + 1*32768 + off) = zl;
        *(__nv_bfloat16*)(smc + 2*32768 + off) = dh;
        *(__nv_bfloat16*)(smc + 3*32768 + off) = dl;
    }
    if (tid < 128) kvs[tid] = g_kv[tid];
    __syncthreads();

    // cp.async fill mapping: thread -> (row, segs tid&3 and +4); 2 x 16B per thread
    const int crow = tid >> 2, cs0 = tid & 3;
    const unsigned crsw = (unsigned)((crow & 7) << 4);
    const unsigned cd0 = (unsigned)(crow*128) + (((unsigned)cs0*16) ^ crsw);
    const unsigned cd1 = (unsigned)(crow*128) + (((unsigned)(cs0+4)*16) ^ crsw);

    for (int tile = blockIdx.x; tile < NTILES; tile += gridDim.x) {
        const size_t rbase = (size_t)tile * 128;

        const unsigned mlo = (etype[rbase + wrow*16 + (lane >> 2)]     != 0) ? 0xffffffffu : 0u;
        const unsigned mhi = (etype[rbase + wrow*16 + 8 + (lane >> 2)] != 0) ? 0xffffffffu : 0u;

        float accf[4][2][4];
#pragma unroll
        for (int g = 0; g < 4; g++)
#pragma unroll
            for (int s = 0; s < 2; s++)
#pragma unroll
                for (int q = 0; q < 4; q++) accf[g][s][q] = 0.f;

        float pacc = 0.f;   // partial dot h[prow] . kv over seg half

        // prologue: chunk 0 -> buf0
        {
            const float* src = hmail + (rbase + crow)*128;
            CP_ASYNC16(smb + K2_AB + cd0, (const void*)(src + cs0*4));
            CP_ASYNC16(smb + K2_AB + cd1, (const void*)(src + (cs0+4)*4));
            CP_COMMIT();
        }

        for (int c = 0; c < 4; c++) {
            if (c < 3) {
                const float* src = hmail + (rbase + crow)*128 + (c+1)*32;
                unsigned dst = smb + K2_AB + (unsigned)(((c+1) & 1)*16384);
                CP_ASYNC16(dst + cd0, (const void*)(src + cs0*4));
                CP_ASYNC16(dst + cd1, (const void*)(src + (cs0+4)*4));
                CP_COMMIT();
                CP_WAIT1();
            } else {
                CP_WAIT0();
            }
            __syncthreads();
            const int abuf = K2_AB + (c & 1)*16384;
            // ---- MMA on chunk c (32 k = 2 kk steps); A fp32 + in-register split ----
            {
                const int rlo = wrow*16 + (lane >> 2);
                const int rhi = rlo + 8;
                const unsigned swlo = (unsigned)((rlo & 7) << 4);
                const unsigned swhi = (unsigned)((rhi & 7) << 4);
                const int bn_l = (lane & 7) + (lane >> 4) * 8;
                const int bkb_l = ((lane >> 3) & 1) * 16;
#pragma unroll
                for (int kk = 0; kk < 2; kk++) {
                    const unsigned kb = (unsigned)(kk*64 + (lane & 3)*8);
                    float2 v0 = *(const float2*)(smc + abuf + rlo*128 + (kb ^ swlo));
                    float2 v1 = *(const float2*)(smc + abuf + rhi*128 + (kb ^ swhi));
                    float2 v2 = *(const float2*)(smc + abuf + rlo*128 + ((kb + 32) ^ swlo));
                    float2 v3 = *(const float2*)(smc + abuf + rhi*128 + ((kb + 32) ^ swhi));
                    unsigned ah[4], al[4], aeh[4], ael[4];
                    split2(v0.x, v0.y, ah[0], al[0]);
                    split2(v1.x, v1.y, ah[1], al[1]);
                    split2(v2.x, v2.y, ah[2], al[2]);
                    split2(v3.x, v3.y, ah[3], al[3]);
                    aeh[0] = ah[0] & mlo; aeh[1] = ah[1] & mhi;
                    aeh[2] = ah[2] & mlo; aeh[3] = ah[3] & mhi;
                    ael[0] = al[0] & mlo; ael[1] = al[1] & mhi;
                    ael[2] = al[2] & mlo; ael[3] = al[3] & mhi;
                    const int bkb = c*64 + kk*32 + bkb_l;
#pragma unroll
                    for (int g = 0; g < 4; g++) {
                        int bn = ch*64 + g*16 + bn_l;
                        unsigned boff = (unsigned)(bn*256) +
                                        ((unsigned)bkb ^ ((unsigned)(bn & 7) << 4));
                        unsigned zh[4], zl[4], dh[4], dl[4];
                        ldsm4(zh, smb + 0*32768 + boff);
                        ldsm4(zl, smb + 1*32768 + boff);
                        ldsm4(dh, smb + 2*32768 + boff);
                        ldsm4(dl, smb + 3*32768 + boff);
#pragma unroll
                        for (int s = 0; s < 2; s++) {
                            mma16816(accf[g][s], ah,  zh[s*2], zh[s*2+1]);
                            mma16816(accf[g][s], ah,  zl[s*2], zl[s*2+1]);
                            mma16816(accf[g][s], al,  zh[s*2], zh[s*2+1]);
                            mma16816(accf[g][s], aeh, dh[s*2], dh[s*2+1]);
                            mma16816(accf[g][s], aeh, dl[s*2], dl[s*2+1]);
                            mma16816(accf[g][s], ael, dh[s*2], dh[s*2+1]);
                        }
                    }
                }
            }
            // ---- p partial dots (fp32): row = wrow*16 + (lane>>1), half seg = lane&1 ----
            {
                const int pr = wrow*16 + (lane >> 1);
                const int seg = lane & 1;
                const unsigned psw = (unsigned)((pr & 7) << 4);
#pragma unroll
                for (int i = 0; i < 4; i++) {
                    float4 av = *(const float4*)(smc + abuf + pr*128 +
                                                 (((unsigned)((seg*4+i)*16)) ^ psw));
                    const float* kp = kvs + c*32 + seg*16 + i*4;
                    pacc += av.x*kp[0] + av.y*kp[1] + av.z*kp[2] + av.w*kp[3];
                }
            }
            __syncthreads();   // all warps done with buf (c&1) before refill
        }

        // finalize p: combine seg halves, publish per-row
        pacc += shflr(pacc, 1);
        if ((lane & 1) == 0) pb[wrow*16 + (lane >> 1)] = pacc;
        __syncthreads();

        const int rlo = wrow*16 + (lane >> 2);     // local mail row (node0)
        const int rhi = rlo + 8;                   // node1
        const int node0 = tile*TN + wrow*2, node1 = node0 + 1;

        // ---- f epilogue: f = sigmoid(accf); c_red = sum over 8 mail rows ----
#pragma unroll
        for (int g = 0; g < 4; g++)
#pragma unroll
            for (int s = 0; s < 2; s++) {
                int col = ch*64 + g*16 + s*8 + (lane & 3)*2;
                float2 c0 = *(const float2*)(cmail + (rbase + rlo)*128 + col);
                float2 c1 = *(const float2*)(cmail + (rbase + rhi)*128 + col);
                float v0 = c0.x / (1.f + expf(-accf[g][s][0]));
                float v1 = c0.y / (1.f + expf(-accf[g][s][1]));
                float v2 = c1.x / (1.f + expf(-accf[g][s][2]));
                float v3 = c1.y / (1.f + expf(-accf[g][s][3]));
#pragma unroll
                for (int m = 4; m < 32; m <<= 1) {
                    v0 += shflr(v0, m); v1 += shflr(v1, m);
                    v2 += shflr(v2, m); v3 += shflr(v3, m);
                }
                if (lane < 4) {
                    int cc = ch*64 + g*16 + s*8 + lane*2;
                    *(float2*)(g_cred + (size_t)node0*128 + cc) = make_float2(v0, v1);
                } else if (lane < 8) {
                    int cc = ch*64 + g*16 + s*8 + (lane - 4)*2;
                    *(float2*)(g_cred + (size_t)node1*128 + cc) = make_float2(v2, v3);
                }
            }

        // ---- softmax coefficients (per mail row) ----
        float p_lo = pb[rlo];
        float p_hi = pb[rhi];
        float e_lo = (float)etype[rbase + rlo];
        float e_hi = (float)etype[rbase + rhi];
        float sc_lo = tanhf(g_px[node0] + p_lo);
        float sc_hi = tanhf(g_px[node1] + p_hi);

        float mx0 = sc_lo, mx1 = sc_hi, sm0 = e_lo, sm1 = e_hi;
#pragma unroll
        for (int m = 4; m < 32; m <<= 1) {
            mx0 = fmaxf(mx0, shflr(mx0, m));
            mx1 = fmaxf(mx1, shflr(mx1, m));
            sm0 += shflr(sm0, m);
            sm1 += shflr(sm1, m);
        }
        float ex0 = expf(sc_lo - mx0), ex1 = expf(sc_hi - mx1);
        float se0 = ex0, se1 = ex1;
#pragma unroll
        for (int m = 4; m < 32; m <<= 1) { se0 += shflr(se0, m); se1 += shflr(se1, m); }
        float w0 = ex0 / se0, w1 = ex1 / se1;
        float mod0 = sm0 * 0.125f, mod1 = sm1 * 0.125f;
        float c1_lo = w0 * (1.f - mod0) * e_lo;        // node0, mail (lane>>2)
        float c0_lo = w0 * mod0 * (1.f - e_lo);
        float c1_hi = w1 * (1.f - mod1) * e_hi;        // node1, mail (lane>>2)
        float c0_hi = w1 * mod1 * (1.f - e_hi);

        // ---- u-sums: u = sum over 8 mails of coef * h_mail row; each lane 4 cols ----
        {
            float4 u0a = make_float4(0.f,0.f,0.f,0.f), u1a = u0a, u0b = u0a, u1b = u0a;
            const float* hm0 = hmail + (rbase + wrow*16)*128 + lane*4;
#pragma unroll
            for (int k = 0; k < 8; k++) {
                float c0n0 = __shfl_sync(0xffffffffu, c0_lo, k*4);
                float c1n0 = __shfl_sync(0xffffffffu, c1_lo, k*4);
                float c0n1 = __shfl_sync(0xffffffffu, c0_hi, k*4);
                float c1n1 = __shfl_sync(0xffffffffu, c1_hi, k*4);
                float4 h0 = *(const float4*)(hm0 + (size_t)k*128);
                float4 h1 = *(const float4*)(hm0 + (size_t)(k+8)*128);
                u0a.x += c0n0*h0.x; u0a.y += c0n0*h0.y; u0a.z += c0n0*h0.z; u0a.w += c0n0*h0.w;
                u1a.x += c1n0*h0.x; u1a.y += c1n0*h0.y; u1a.z += c1n0*h0.z; u1a.w += c1n0*h0.w;
                u0b.x += c0n1*h1.x; u0b.y += c0n1*h1.y; u0b.z += c0n1*h1.z; u0b.w += c0n1*h1.w;
                u1b.x += c1n1*h1.x; u1b.y += c1n1*h1.y; u1b.z += c1n1*h1.z; u1b.w += c1n1*h1.w;
            }
            unsigned hi, lo;
            size_t ro0 = (size_t)node0 * 384, ro1 = (size_t)node1 * 384;
            int cc = lane*4;
            split2(u0a.x, u0a.y, hi, lo);
            *(unsigned*)(g_Zh + ro0 + cc) = hi;     *(unsigned*)(g_Zl + ro0 + cc) = lo;
            split2(u0a.z, u0a.w, hi, lo);
            *(unsigned*)(g_Zh + ro0 + cc + 2) = hi; *(unsigned*)(g_Zl + ro0 + cc + 2) = lo;
            split2(u1a.x, u1a.y, hi, lo);
            *(unsigned*)(g_Zh + ro0 + 128 + cc) = hi;     *(unsigned*)(g_Zl + ro0 + 128 + cc) = lo;
            split2(u1a.z, u1a.w, hi, lo);
            *(unsigned*)(g_Zh + ro0 + 128 + cc + 2) = hi; *(unsigned*)(g_Zl + ro0 + 128 + cc + 2) = lo;
            split2(u0b.x, u0b.y, hi, lo);
            *(unsigned*)(g_Zh + ro1 + cc) = hi;     *(unsigned*)(g_Zl + ro1 + cc) = lo;
            split2(u0b.z, u0b.w, hi, lo);
            *(unsigned*)(g_Zh + ro1 + cc + 2) = hi; *(unsigned*)(g_Zl + ro1 + cc + 2) = lo;
            split2(u1b.x, u1b.y, hi, lo);
            *(unsigned*)(g_Zh + ro1 + 128 + cc) = hi;     *(unsigned*)(g_Zl + ro1 + 128 + cc) = lo;
            split2(u1b.z, u1b.w, hi, lo);
            *(unsigned*)(g_Zh + ro1 + 128 + cc + 2) = hi; *(unsigned*)(g_Zl + ro1 + 128 + cc + 2) = lo;
        }
        __syncthreads();   // pb (aliases buf0) fully read before next tile's prologue
    }
}

// ---------------- K3a (mma.sync bf16, 3-term, cp.async double-buffered A) ----------------
// SMEM: Bh 96K | Bl 96K | A bufs 2 x (Ah 8K + Al 8K) = 229376 B
#define K3_BL   98304
#define K3_AB   196608
#define K3_SMEM 229376
__global__ void __launch_bounds__(512, 1)
k3a(const float* __restrict__ biou) {
    extern __shared__ char smc[];
    const unsigned smb = smem_u32(smc);
    const int tid = threadIdx.x, wid = tid >> 5, lane = tid & 31;
    const int wrow = wid & 7, ch = wid >> 3;
    const int jb = blockIdx.x * 128;           // output col block
    const unsigned AB = smb + K3_AB;

    // B fill: B[n][k] = Gp[k][jb+n], bf16 hi/lo, row stride 768B, XOR swizzle
    for (int idx = tid; idx < 128*384; idx += 512) {
        int k = idx % 384, n = idx / 384;
        float v = g_Gp[k*384 + jb + n];
        __nv_bfloat16 bh = __float2bfloat16_rn(v);
        __nv_bfloat16 bl = __float2bfloat16_rn(v - __bfloat162float(bh));
        unsigned off = (unsigned)(n*768 + ((2*k) ^ ((n & 7) << 4)));
        *(__nv_bfloat16*)(smc + off)          = bh;
        *(__nv_bfloat16*)(smc + K3_BL + off)  = bl;
    }
    __syncthreads();

    const int crow = tid >> 2, cseg = tid & 3;
    const unsigned csw = ((unsigned)((crow >> 1) & 3)) << 4;
    const unsigned cdo = (unsigned)(crow*64) + (((unsigned)cseg*16) ^ csw);

    for (int rt = blockIdx.y; rt < 391; rt += gridDim.y) {
        const size_t rbase = (size_t)rt * 128;

        {
            const size_t go = (rbase + crow)*384 + cseg*8;
            CP_ASYNC16(AB + cdo,        (const void*)(g_Zh + go));
            CP_ASYNC16(AB + 8192 + cdo, (const void*)(g_Zl + go));
            CP_COMMIT();
        }

        float acc[4][2][4];
#pragma unroll
        for (int g = 0; g < 4; g++)
#pragma unroll
            for (int s = 0; s < 2; s++)
#pragma unroll
                for (int q = 0; q < 4; q++) acc[g][s][q] = 0.f;

        for (int c = 0; c < 12; c++) {
            if (c < 11) {
                const size_t go = (rbase + crow)*384 + (c+1)*32 + cseg*8;
                unsigned dst = AB + (unsigned)(((c+1) & 1)*16384) + cdo;
                CP_ASYNC16(dst,        (const void*)(g_Zh + go));
                CP_ASYNC16(dst + 8192, (const void*)(g_Zl + go));
                CP_COMMIT();
                CP_WAIT1();
            } else {
                CP_WAIT0();
            }
            __syncthreads();
            {
                const int arow = wrow*16 + (lane & 7) + ((lane >> 3) & 1) * 8;
                const unsigned arsw = ((unsigned)((arow >> 1) & 3)) << 4;
                const int bn_l = (lane & 7) + (lane >> 4) * 8;
                const int bkb_l = ((lane >> 3) & 1) * 16;
                const unsigned abase = AB + (unsigned)((c & 1)*16384);
#pragma unroll
                for (int kk = 0; kk < 2; kk++) {
                    unsigned akb = (unsigned)(kk*32 + (lane >> 4) * 16);
                    unsigned aoff = (unsigned)(arow*64) + (akb ^ arsw);
                    unsigned ah[4], al[4];
                    ldsm4(ah, abase + aoff);
                    ldsm4(al, abase + 8192 + aoff);
                    const int bkb = c*64 + kk*32 + bkb_l;
#pragma unroll
                    for (int g = 0; g < 4; g++) {
                        int bn = ch*64 + g*16 + bn_l;
                        unsigned boff = (unsigned)(bn*768) +
                                        ((unsigned)bkb ^ ((unsigned)(bn & 7) << 4));
                        unsigned bh[4], bl[4];
                        ldsm4(bh, smb + boff);
                        ldsm4(bl, smb + K3_BL + boff);
#pragma unroll
                        for (int s = 0; s < 2; s++) {
                            mma16816(acc[g][s], ah, bh[s*2], bh[s*2+1]);
                            mma16816(acc[g][s], ah, bl[s*2], bl[s*2+1]);
                            mma16816(acc[g][s], al, bh[s*2], bh[s*2+1]);
                        }
                    }
                }
            }
            __syncthreads();
        }

        {
            const size_t rlo = rbase + wrow*16 + (lane >> 2);
            const size_t rhi = rlo + 8;
#pragma unroll
            for (int g = 0; g < 4; g++)
#pragma unroll
                for (int s = 0; s < 2; s++) {
                    int c = ch*64 + g*16 + s*8 + (lane & 3)*2;
                    float2 bi = *(const float2*)(biou + jb + c);
                    *(float2*)(g_IOU + rlo*384 + jb + c) =
                        make_float2(acc[g][s][0] + bi.x, acc[g][s][1] + bi.y);
                    *(float2*)(g_IOU + rhi*384 + jb + c) =
                        make_float2(acc[g][s][2] + bi.x, acc[g][s][3] + bi.y);
                }
        }
    }
}

// ---------------- K3b: gates -> out ----------------
__global__ void k3b(float* __restrict__ out) {
    int idx = blockIdx.x * blockDim.x + threadIdx.x;
    if (idx >= NN*32) return;
    int n = idx >> 5;
    int j = (idx & 31) * 4;
    const float* r = g_IOU + (size_t)n * 384;
    float4 iv = *(const float4*)(r + j);
    float4 ov = *(const float4*)(r + 128 + j);
    float4 uv = *(const float4*)(r + 256 + j);
    float4 cr = *(const float4*)(g_cred + (size_t)n*128 + j);
    float4 hc, cc;
    {
        float ig, og, ug, c, h;
        ig = 1.f/(1.f+expf(-iv.x)); og = 1.f/(1.f+expf(-ov.x)); ug = tanhf(uv.x);
        c = ig*ug + cr.x; h = og*tanhf(c); hc.x = h; cc.x = c;
        ig = 1.f/(1.f+expf(-iv.y)); og = 1.f/(1.f+expf(-ov.y)); ug = tanhf(uv.y);
        c = ig*ug + cr.y; h = og*tanhf(c); hc.y = h; cc.y = c;
        ig = 1.f/(1.f+expf(-iv.z)); og = 1.f/(1.f+expf(-ov.z)); ug = tanhf(uv.z);
        c = ig*ug + cr.z; h = og*tanhf(c); hc.z = h; cc.z = c;
        ig = 1.f/(1.f+expf(-iv.w)); og = 1.f/(1.f+expf(-ov.w)); ug = tanhf(uv.w);
        c = ig*ug + cr.w; h = og*tanhf(c); hc.w = h; cc.w = c;
    }
    *(float4*)(out + (size_t)n*128 + j) = hc;
    *(float4*)(out + (size_t)NN*128 + (size_t)n*128 + j) = cc;
}

// ---------------- launcher ----------------
extern "C" void kernel_launch(void* const* d_in, const int* in_sizes, int n_in,
                              void* d_out, int out_size) {
    const float* x      = (const float*)d_in[0];
    const float* h_mail = (const float*)d_in[1];
    const float* c_mail = (const float*)d_in[2];
    const float* Wiou   = (const float*)d_in[3];
    const float* Uiou   = (const float*)d_in[4];
    const float* biou   = (const float*)d_in[5];
    const float* Of     = (const float*)d_in[6];
    const float* Zf     = (const float*)d_in[7];
    const float* Qf     = (const float*)d_in[8];
    const float* Kf     = (const float*)d_in[9];
    const float* vf     = (const float*)d_in[10];
    const float* Wa     = (const float*)d_in[11];
    const float* Wd     = (const float*)d_in[12];
    const float* Vf     = (const float*)d_in[13];
    const int*   etype  = (const int*)d_in[14];
    float* out = (float*)d_out;

    cudaFuncSetAttribute(k2,  cudaFuncAttributeMaxDynamicSharedMemorySize, K2_SMEM);
    cudaFuncSetAttribute(k3a, cudaFuncAttributeMaxDynamicSharedMemorySize, K3_SMEM);

    k1a<<<128, 256>>>(Wa, Wd, vf);
    k1b<<<577, 256>>>(Uiou, Wiou, Qf, Kf, Vf);
    k1bb<<<576, 256>>>(Kf);
    k1c<<<6250, 256>>>(x);
    k2<<<148, 512, K2_SMEM>>>(h_mail, c_mail, Of, Zf, etype);
    k3a<<<dim3(3, 49), 512, K3_SMEM>>>(biou);
    k3b<<<6250, 256>>>(out);
}